// round 1
// baseline (speedup 1.0000x reference)
#include <cuda_runtime.h>

#define FULL_MASK 0xffffffffu

constexpr int L               = 32;
constexpr int ROWS_PER_BLOCK  = 128;   // one row per thread
constexpr int THREADS         = 128;
constexpr int SMEM_STRIDE     = 33;    // padded: conflict-free STS and LDS
constexpr int MAX_BLOCKS      = 65536;

__device__ float g_partial[MAX_BLOCKS];

__global__ __launch_bounds__(THREADS)
void qfd2_main_kernel(const float* __restrict__ logits,
                      const float* __restrict__ D,
                      int B)
{
    __shared__ float sL[ROWS_PER_BLOCK * SMEM_STRIDE];
    __shared__ float sD[ROWS_PER_BLOCK * SMEM_STRIDE];
    __shared__ float wsum[THREADS / 32];

    const int tid = threadIdx.x;
    const long long row0 = (long long)blockIdx.x * ROWS_PER_BLOCK;

    // ---- Cooperative coalesced staging: gmem float4 -> padded smem ----
    const float4* gL = (const float4*)logits;
    const float4* gD = (const float4*)D;
    const long long f4_base  = row0 * (L / 4);
    const long long f4_total = (long long)B * (L / 4);

    #pragma unroll
    for (int it = 0; it < (ROWS_PER_BLOCK * (L / 4)) / THREADS; ++it) {
        int j = tid + it * THREADS;                  // 0 .. 1023
        long long gidx = f4_base + j;
        if (gidx >= f4_total) gidx = f4_total - 1;   // clamp (tail rows zeroed later)
        float4 vL = __ldg(&gL[gidx]);
        float4 vD = __ldg(&gD[gidx]);
        int r = j >> 3;                              // row within tile (8 float4/row)
        int c = (j & 7) << 2;                        // column
        int s = r * SMEM_STRIDE + c;
        sL[s + 0] = vL.x; sL[s + 1] = vL.y; sL[s + 2] = vL.z; sL[s + 3] = vL.w;
        sD[s + 0] = vD.x; sD[s + 1] = vD.y; sD[s + 2] = vD.z; sD[s + 3] = vD.w;
    }
    __syncthreads();

    // ---- Per-thread row compute (conflict-free LDS: bank = (lane + i) % 32) ----
    const float* rL = &sL[tid * SMEM_STRIDE];
    const float* rD = &sD[tid * SMEM_STRIDE];

    float e[L];
    float m = -3.402823466e38f;
    #pragma unroll
    for (int i = 0; i < L; ++i) { e[i] = rL[i]; m = fmaxf(m, e[i]); }

    float denom = 0.f;
    #pragma unroll
    for (int i = 0; i < L; ++i) { e[i] = __expf(e[i] - m); denom += e[i]; }
    const float inv = __fdividef(1.0f, denom);

    // Q_i = D_i - softmax_i ; P = prefix sums of Q ; S = P_{L-1}
    // per_row = S^2 - (2/(L-1)) * (S * sum_{m<L-1} P_m - sum_{m<L-1} P_m^2)
    float P = 0.f, sumP = 0.f, sumP2 = 0.f;
    #pragma unroll
    for (int i = 0; i < L; ++i) {
        float q = fmaf(-e[i], inv, rD[i]);
        P += q;
        if (i < L - 1) {
            sumP += P;
            sumP2 = fmaf(P, P, sumP2);
        }
    }
    const float S = P;
    float per_row = S * S - (2.0f / 31.0f) * (S * sumP - sumP2);
    if (row0 + tid >= B) per_row = 0.f;

    // ---- Deterministic block reduction ----
    #pragma unroll
    for (int off = 16; off; off >>= 1)
        per_row += __shfl_xor_sync(FULL_MASK, per_row, off);

    const int lane = tid & 31, wid = tid >> 5;
    if (lane == 0) wsum[wid] = per_row;
    __syncthreads();
    if (tid == 0) {
        float b = 0.f;
        #pragma unroll
        for (int w = 0; w < THREADS / 32; ++w) b += wsum[w];
        g_partial[blockIdx.x] = b;
    }
}

__global__ __launch_bounds__(1024)
void qfd2_finalize_kernel(int nblocks, int B, float* __restrict__ out)
{
    __shared__ float wsum[32];
    const int tid = threadIdx.x;

    float s = 0.f;
    for (int i = tid; i < nblocks; i += blockDim.x) s += g_partial[i];

    #pragma unroll
    for (int off = 16; off; off >>= 1)
        s += __shfl_xor_sync(FULL_MASK, s, off);

    const int lane = tid & 31, wid = tid >> 5;
    if (lane == 0) wsum[wid] = s;
    __syncthreads();

    if (tid < 32) {
        float v = (tid < (int)(blockDim.x >> 5)) ? wsum[tid] : 0.f;
        #pragma unroll
        for (int off = 16; off; off >>= 1)
            v += __shfl_xor_sync(FULL_MASK, v, off);
        if (tid == 0) out[0] = v / (float)B;
    }
}

extern "C" void kernel_launch(void* const* d_in, const int* in_sizes, int n_in,
                              void* d_out, int out_size)
{
    const float* logits = (const float*)d_in[0];   // D_pred_logit [B, 32]
    const float* D      = (const float*)d_in[1];   // D            [B, 32]
    float* out          = (float*)d_out;           // scalar f32

    const int B = in_sizes[0] / L;
    int blocks = (B + ROWS_PER_BLOCK - 1) / ROWS_PER_BLOCK;
    if (blocks > MAX_BLOCKS) blocks = MAX_BLOCKS;  // B=1048576 -> 8192, safe

    qfd2_main_kernel<<<blocks, THREADS>>>(logits, D, B);
    qfd2_finalize_kernel<<<1, 1024>>>(blocks, B, out);
}